// round 9
// baseline (speedup 1.0000x reference)
#include <cuda_runtime.h>
#include <cstdint>

// ---------------------------------------------------------------------------
// AdaptiveDCA: pre-round -> qkv GEMM (mma.sync tf32 + cp.async) -> attention
// x (8,512,64,64), w_qkv (1536,512), w_gate (4,512), b_gate (4) -> out fp32
// GEMM tile 128x256x8 (traffic-optimized); compute_100-safe (no tcgen05).
// ---------------------------------------------------------------------------

#define B_   8
#define C_   512
#define HW_  4096
#define M_   1536
#define K_   512

__device__ float g_qkv[(size_t)B_ * M_ * HW_];     // ~201 MB scratch
__device__ float g_xtf[(size_t)B_ * C_ * HW_];     // tf32-rounded X (67 MB)
__device__ float g_wtf[(size_t)M_ * K_];           // tf32-rounded W (3 MB)
__device__ float g_pooled[B_ * C_];
__device__ float g_gate[B_ * 4];

__device__ __forceinline__ uint32_t f2tf32(float x) {
    uint32_t r;
    asm("cvt.rna.tf32.f32 %0, %1;" : "=r"(r) : "f"(x));
    return r;
}
__device__ __forceinline__ uint32_t smem_u32(const void* p) {
    uint32_t a;
    asm("{ .reg .u64 t; cvta.to.shared.u64 t, %1; cvt.u32.u64 %0, t; }"
        : "=r"(a) : "l"(p));
    return a;
}

#define CP_ASYNC16(dst, src) \
    asm volatile("cp.async.cg.shared.global [%0], [%1], 16;" \
                 :: "r"(dst), "l"(src) : "memory")
#define CP_COMMIT() asm volatile("cp.async.commit_group;" ::: "memory")
#define CP_WAIT1()  asm volatile("cp.async.wait_group 1;" ::: "memory")

__device__ __forceinline__ void mma_tf32(
    float& c0, float& c1, float& c2, float& c3,
    uint32_t a0, uint32_t a1, uint32_t a2, uint32_t a3,
    uint32_t b0, uint32_t b1)
{
    asm volatile(
        "mma.sync.aligned.m16n8k8.row.col.f32.tf32.tf32.f32 "
        "{%0,%1,%2,%3}, {%4,%5,%6,%7}, {%8,%9}, {%0,%1,%2,%3};"
        : "+f"(c0), "+f"(c1), "+f"(c2), "+f"(c3)
        : "r"(a0), "r"(a1), "r"(a2), "r"(a3), "r"(b0), "r"(b1));
}

// ---------------------------------------------------------------------------
// Pre-round fp32 -> tf32 bits (rna). which: 0 -> g_xtf, 1 -> g_wtf
// ---------------------------------------------------------------------------
__global__ __launch_bounds__(256) void preround_kernel(
    const float* __restrict__ in, int which, int n4)
{
    const int i = blockIdx.x * 256 + threadIdx.x;
    if (i < n4) {
        float* out = which ? g_wtf : g_xtf;
        float4 v = ((const float4*)in)[i];
        uint4 r = make_uint4(f2tf32(v.x), f2tf32(v.y), f2tf32(v.z), f2tf32(v.w));
        ((uint4*)out)[i] = r;
    }
}

// ---------------------------------------------------------------------------
// TF32 GEMM: qkv[b,o,n] = sum_c W[o,c] * X[b,c,n]
// BM=128, BN=256, BK=8; 256 threads, 8 warps (2m x 4n), warp tile 64x64.
// SMEM: A [2][128][12] floats (pad12: banks 12*lr+lc distinct),
//       B [2][8][264] floats (264%32=8: banks lc*8+lr distinct). 29184 B.
// ---------------------------------------------------------------------------
#define BKg     8
#define BNg     256
#define LDAP_   12
#define LDB_    264
#define A_ST    (128 * LDAP_ * 4)          // 6144 B per stage
#define B_ST    (BKg * LDB_ * 4)           // 8448 B per stage
#define B_OFF   (2 * A_ST)                 // 12288
#define SM_TOT  (B_OFF + 2 * B_ST)         // 29184

__global__ __launch_bounds__(256) void gemm_qkv_tc()
{
    extern __shared__ uint8_t smem[];
    const uint32_t sbase = smem_u32(smem);
    float* const smf = (float*)smem;

    const int tid = threadIdx.x;
    const int bz  = blockIdx.z;
    const int bm0 = blockIdx.y * 128;
    const int bn0 = blockIdx.x * BNg;

    const float* Ag = g_wtf + (size_t)bm0 * K_;               // [m][k] k-contig
    const float* Bg = g_xtf + (size_t)bz * C_ * HW_ + bn0;    // [k][n] n-contig
    float* Cg = g_qkv + ((size_t)bz * M_ + bm0) * HW_ + bn0;

    // cp.async maps: A 256 chunks (2/row of 8 floats), B 512 chunks (64/row)
    const int a_row = tid >> 1;        // 0..127
    const int a_q   = tid & 1;         // 16B half of the 32B row
    const int b_c0  = tid * 2;         // B chunks b_c0, b_c0+1
    const int b_r0  = b_c0 >> 6;       // 0..7
    const int b_q0  = b_c0 & 63;

    // warp/fragment maps: 2m x 4n warps, warp tile 64x64
    const int wid    = tid >> 5;
    const int lane   = tid & 31;
    const int warp_m = (wid & 1) * 64;
    const int warp_n = (wid >> 1) * 64;
    const int lr = lane >> 2;
    const int lc = lane & 3;

    float acc[4][8][4];
    #pragma unroll
    for (int mt = 0; mt < 4; mt++)
        #pragma unroll
        for (int nt = 0; nt < 8; nt++)
            #pragma unroll
            for (int r = 0; r < 4; r++) acc[mt][nt][r] = 0.f;

    auto issue_stage = [&](int s, int k0) {
        {
            uint32_t d = sbase + s * A_ST + (a_row * LDAP_ + a_q * 4) * 4;
            CP_ASYNC16(d, Ag + (size_t)a_row * K_ + k0 + a_q * 4);
        }
        {
            uint32_t d0 = sbase + B_OFF + s * B_ST + (b_r0 * LDB_ + b_q0 * 4) * 4;
            CP_ASYNC16(d0, Bg + (size_t)(k0 + b_r0) * HW_ + b_q0 * 4);
            const int c1 = b_c0 + 1, r1 = c1 >> 6, q1 = c1 & 63;
            uint32_t d1 = sbase + B_OFF + s * B_ST + (r1 * LDB_ + q1 * 4) * 4;
            CP_ASYNC16(d1, Bg + (size_t)(k0 + r1) * HW_ + q1 * 4);
        }
        CP_COMMIT();
    };

    issue_stage(0, 0);
    issue_stage(1, BKg);

    const int NITER = K_ / BKg;   // 64
    for (int iter = 0; iter < NITER; iter++) {
        const int st = iter & 1;
        CP_WAIT1();
        __syncthreads();

        const float* As = smf + st * (A_ST / 4);
        const float* Bs = smf + (B_OFF + st * B_ST) / 4;

        uint32_t af[4][4], bf[8][2];
        #pragma unroll
        for (int mt = 0; mt < 4; mt++) {
            const int r0 = warp_m + mt * 16 + lr;
            af[mt][0] = __float_as_uint(As[r0 * LDAP_ + lc]);
            af[mt][1] = __float_as_uint(As[(r0 + 8) * LDAP_ + lc]);
            af[mt][2] = __float_as_uint(As[r0 * LDAP_ + lc + 4]);
            af[mt][3] = __float_as_uint(As[(r0 + 8) * LDAP_ + lc + 4]);
        }
        #pragma unroll
        for (int nt = 0; nt < 8; nt++) {
            const int nb = warp_n + nt * 8 + lr;
            bf[nt][0] = __float_as_uint(Bs[lc * LDB_ + nb]);
            bf[nt][1] = __float_as_uint(Bs[(lc + 4) * LDB_ + nb]);
        }
        #pragma unroll
        for (int mt = 0; mt < 4; mt++)
            #pragma unroll
            for (int nt = 0; nt < 8; nt++)
                mma_tf32(acc[mt][nt][0], acc[mt][nt][1],
                         acc[mt][nt][2], acc[mt][nt][3],
                         af[mt][0], af[mt][1], af[mt][2], af[mt][3],
                         bf[nt][0], bf[nt][1]);

        __syncthreads();
        if (iter + 2 < NITER) issue_stage(st, (iter + 2) * BKg);
        else CP_COMMIT();   // keep wait_group counts consistent
    }

    // epilogue: c0/c1 at (row, 2lc), c2/c3 at (row+8, 2lc)
    #pragma unroll
    for (int mt = 0; mt < 4; mt++) {
        const int r0 = warp_m + mt * 16 + lr;
        #pragma unroll
        for (int nt = 0; nt < 8; nt++) {
            const int cbase = warp_n + nt * 8 + 2 * lc;
            float2 v01 = make_float2(acc[mt][nt][0], acc[mt][nt][1]);
            float2 v23 = make_float2(acc[mt][nt][2], acc[mt][nt][3]);
            *(float2*)(Cg + (size_t)r0 * HW_ + cbase)       = v01;
            *(float2*)(Cg + (size_t)(r0 + 8) * HW_ + cbase) = v23;
        }
    }
}

// ---------------------------------------------------------------------------
// Global average pool (float4 vectorized)
// ---------------------------------------------------------------------------
__global__ __launch_bounds__(256) void pool_kernel(const float* __restrict__ X)
{
    const int bc = blockIdx.x;
    const float4* xp = (const float4*)(X + (size_t)bc * HW_);
    float sum = 0.f;
    for (int i = threadIdx.x; i < HW_ / 4; i += 256) {
        float4 v = xp[i];
        sum += (v.x + v.y) + (v.z + v.w);
    }
    #pragma unroll
    for (int o = 16; o > 0; o >>= 1) sum += __shfl_xor_sync(0xFFFFFFFFu, sum, o);
    __shared__ float sm[8];
    if ((threadIdx.x & 31) == 0) sm[threadIdx.x >> 5] = sum;
    __syncthreads();
    if (threadIdx.x == 0) {
        float t = 0.f;
        #pragma unroll
        for (int i = 0; i < 8; i++) t += sm[i];
        g_pooled[bc] = t * (1.0f / HW_);
    }
}

// ---------------------------------------------------------------------------
// Gate softmax
// ---------------------------------------------------------------------------
__global__ void gate_kernel(const float* __restrict__ Wg, const float* __restrict__ bg)
{
    __shared__ float lg[32];
    const int t = threadIdx.x;
    const int b = t >> 2, i = t & 3;
    float dot = bg[i];
    const float* p = g_pooled + b * C_;
    const float* w = Wg + i * C_;
    for (int c = 0; c < C_; c++) dot += p[c] * w[c];
    lg[t] = dot;
    __syncthreads();
    if (t < B_) {
        float l0 = lg[t*4+0], l1 = lg[t*4+1], l2 = lg[t*4+2], l3 = lg[t*4+3];
        float m = fmaxf(fmaxf(l0, l1), fmaxf(l2, l3));
        float e0 = expf(l0 - m), e1 = expf(l1 - m), e2 = expf(l2 - m), e3 = expf(l3 - m);
        float inv = 1.0f / (e0 + e1 + e2 + e3);
        g_gate[t*4+0] = e0 * inv;
        g_gate[t*4+1] = e1 * inv;
        g_gate[t*4+2] = e2 * inv;
        g_gate[t*4+3] = e3 * inv;
    }
}

// ---------------------------------------------------------------------------
// Dilated 3x3 attention + gate + write out (zero-padding softmax semantics)
// ---------------------------------------------------------------------------
__global__ __launch_bounds__(256) void attn_kernel(float* __restrict__ out)
{
    const int n = blockIdx.x * 256 + threadIdx.x;
    const int dh = blockIdx.y;
    const int b  = blockIdx.z;
    const int i    = dh >> 1;
    const int head = dh & 1;
    const int dil  = 1 << i;
    const int h = n >> 6, w = n & 63;
    const float scale = 0.125f;

    const size_t base = ((size_t)b * M_ + i * 128 + head * 64) * HW_;
    const float* qp = g_qkv + base;
    const float* kp = g_qkv + base + (size_t)C_ * HW_;
    const float* vp = g_qkv + base + (size_t)2 * C_ * HW_;

    float s[9];
    int   nn[9];
    bool  ok[9];

    {
        float q[64];
        #pragma unroll
        for (int c = 0; c < 64; c++) q[c] = qp[(size_t)c * HW_ + n];

        #pragma unroll
        for (int j = 0; j < 9; j++) {
            const int dy = (j / 3 - 1) * dil;
            const int dx = (j % 3 - 1) * dil;
            const int hh = h + dy, ww = w + dx;
            const bool v_ok = ((unsigned)hh < 64u) && ((unsigned)ww < 64u);
            const int nnj = hh * 64 + ww;
            nn[j] = nnj; ok[j] = v_ok;
            float dot = 0.f;
            if (v_ok) {
                const float* kk = kp + nnj;
                #pragma unroll
                for (int c = 0; c < 64; c++) dot += q[c] * kk[(size_t)c * HW_];
            }
            s[j] = dot * scale;
        }
    }

    float m = s[0];
    #pragma unroll
    for (int j = 1; j < 9; j++) m = fmaxf(m, s[j]);
    float sum = 0.f;
    #pragma unroll
    for (int j = 0; j < 9; j++) { s[j] = expf(s[j] - m); sum += s[j]; }
    const float inv = 1.0f / sum;
    #pragma unroll
    for (int j = 0; j < 9; j++) s[j] *= inv;

    float acc[64];
    #pragma unroll
    for (int c = 0; c < 64; c++) acc[c] = 0.f;
    #pragma unroll
    for (int j = 0; j < 9; j++) {
        if (ok[j]) {
            const float p = s[j];
            const float* vv = vp + nn[j];
            #pragma unroll
            for (int c = 0; c < 64; c++) acc[c] += p * vv[(size_t)c * HW_];
        }
    }

    const float g = g_gate[b * 4 + i];
    float* op = out + ((size_t)b * C_ + i * 128 + head * 64) * HW_ + n;
    #pragma unroll
    for (int c = 0; c < 64; c++) op[(size_t)c * HW_] = g * acc[c];
}

// ---------------------------------------------------------------------------
extern "C" void kernel_launch(void* const* d_in, const int* in_sizes, int n_in,
                              void* d_out, int out_size)
{
    const float* x      = (const float*)d_in[0];
    const float* w_qkv  = (const float*)d_in[1];
    const float* w_gate = (const float*)d_in[2];
    const float* b_gate = (const float*)d_in[3];
    float* out = (float*)d_out;

    // pre-round inputs to tf32 (rna) once (writes g_xtf / g_wtf)
    preround_kernel<<<(B_ * C_ * HW_ / 4 + 255) / 256, 256>>>(x, 0, B_ * C_ * HW_ / 4);
    preround_kernel<<<(M_ * K_ / 4 + 255) / 256, 256>>>(w_qkv, 1, M_ * K_ / 4);

    // qkv GEMM (reads g_wtf/g_xtf, writes g_qkv)
    gemm_qkv_tc<<<dim3(HW_ / BNg, M_ / 128, B_), 256, SM_TOT>>>();

    // gate path
    pool_kernel<<<B_ * C_, 256>>>(x);
    gate_kernel<<<1, 32>>>(w_gate, b_gate);

    // attention + gating + output
    attn_kernel<<<dim3(HW_ / 256, 8, B_), 256>>>(out);
}

// round 10
// speedup vs baseline: 1.4904x; 1.4904x over previous
#include <cuda_runtime.h>
#include <cuda_fp16.h>
#include <cstdint>

// ---------------------------------------------------------------------------
// AdaptiveDCA: half-convert (W) + half-transpose (X) -> fp16 mma GEMM ->
// 4x dilated 3x3 attention -> gated concat
// x (8,512,64,64), w_qkv (1536,512), w_gate (4,512), b_gate (4) -> out fp32
// fp16 m16n8k16 has the same 10-bit mantissa as tf32 -> rel_err unchanged,
// but 2x the tensor-pipe FLOPs per instruction. compute_100-safe.
// ---------------------------------------------------------------------------

#define B_   8
#define C_   512
#define HW_  4096
#define M_   1536
#define K_   512

__device__ float  g_qkv[(size_t)B_ * M_ * HW_];    // ~201 MB scratch
__device__ __half g_xh[(size_t)B_ * HW_ * K_];     // X^T in half [b][n][k], 33.5 MB
__device__ __half g_wh[(size_t)M_ * K_];           // W in half [m][k], 1.5 MB
__device__ float  g_pooled[B_ * C_];
__device__ float  g_gate[B_ * 4];

__device__ __forceinline__ uint32_t smem_u32(const void* p) {
    uint32_t a;
    asm("{ .reg .u64 t; cvta.to.shared.u64 t, %1; cvt.u32.u64 %0, t; }"
        : "=r"(a) : "l"(p));
    return a;
}

#define CP_ASYNC16(dst, src) \
    asm volatile("cp.async.cg.shared.global [%0], [%1], 16;" \
                 :: "r"(dst), "l"(src) : "memory")
#define CP_COMMIT() asm volatile("cp.async.commit_group;" ::: "memory")
#define CP_WAIT1()  asm volatile("cp.async.wait_group 1;" ::: "memory")

__device__ __forceinline__ void mma_f16(
    float& c0, float& c1, float& c2, float& c3,
    uint32_t a0, uint32_t a1, uint32_t a2, uint32_t a3,
    uint32_t b0, uint32_t b1)
{
    asm volatile(
        "mma.sync.aligned.m16n8k16.row.col.f32.f16.f16.f32 "
        "{%0,%1,%2,%3}, {%4,%5,%6,%7}, {%8,%9}, {%0,%1,%2,%3};"
        : "+f"(c0), "+f"(c1), "+f"(c2), "+f"(c3)
        : "r"(a0), "r"(a1), "r"(a2), "r"(a3), "r"(b0), "r"(b1));
}

// ---------------------------------------------------------------------------
// W -> half, [m][k] unchanged layout
// ---------------------------------------------------------------------------
__global__ __launch_bounds__(256) void conv_w_kernel(const float* __restrict__ W)
{
    const int i = blockIdx.x * 256 + threadIdx.x;   // i indexes float4
    if (i < M_ * K_ / 4) {
        float4 v = ((const float4*)W)[i];
        __half2 h0 = __floats2half2_rn(v.x, v.y);
        __half2 h1 = __floats2half2_rn(v.z, v.w);
        ((__half2*)g_wh)[i * 2 + 0] = h0;
        ((__half2*)g_wh)[i * 2 + 1] = h1;
    }
}

// ---------------------------------------------------------------------------
// X [b][c][n] -> half transposed [b][n][k=c]; 32x32 smem tiles
// ---------------------------------------------------------------------------
__global__ __launch_bounds__(256) void transpose_x_kernel(const float* __restrict__ X)
{
    __shared__ float sm[32][33];
    const int b  = blockIdx.z;
    const int c0 = blockIdx.y * 32;
    const int n0 = blockIdx.x * 32;
    const int tx = threadIdx.x;       // 0..31
    const int ty = threadIdx.y;       // 0..7

    const float* xp = X + ((size_t)b * C_ + c0) * HW_ + n0;
    #pragma unroll
    for (int i = 0; i < 4; i++)
        sm[ty + 8 * i][tx] = xp[(size_t)(ty + 8 * i) * HW_ + tx];
    __syncthreads();

    __half* op = g_xh + ((size_t)b * HW_ + n0) * K_ + c0;
    #pragma unroll
    for (int i = 0; i < 4; i++)
        op[(size_t)(ty + 8 * i) * K_ + tx] = __float2half_rn(sm[tx][ty + 8 * i]);
}

// ---------------------------------------------------------------------------
// fp16 GEMM: qkv[b,o,n] = sum_c W[o,c] * X[b,c,n]
// BM=128, BN=128, BK=16; 256 threads, 8 warps (2m x 4n), warp tile 64x32.
// A: [128 m][24 halfs] (16 data + 8 pad; 48B rows), B: [128 n][24 halfs].
// Banks: (12*lr + lc) mod 32 distinct -> conflict-free fragment LDS.
// SMEM: 2 stages x (6144 + 6144) = 24576 B.
// ---------------------------------------------------------------------------
#define BKh     16
#define LDH_    24                     // halfs per row (48 B)
#define H_ST    (128 * LDH_ * 2)       // 6144 B per tile per stage
#define B_OFF   (2 * H_ST)             // 12288 (A stages first)
#define SM_TOT  (4 * H_ST)             // 24576

__global__ __launch_bounds__(256) void gemm_qkv_f16()
{
    extern __shared__ uint8_t smem[];
    const uint32_t sbase = smem_u32(smem);

    const int tid = threadIdx.x;
    const int bz  = blockIdx.z;
    const int bm0 = blockIdx.y * 128;
    const int bn0 = blockIdx.x * 128;

    const __half* Ag = g_wh + (size_t)bm0 * K_;                 // [m][k]
    const __half* Bg = g_xh + ((size_t)bz * HW_ + bn0) * K_;    // [n][k]
    float* Cg = g_qkv + ((size_t)bz * M_ + bm0) * HW_ + bn0;

    // cp.async: 256 chunks per tile (2 per 32B row); 1 A + 1 B chunk/thread
    const int row = tid >> 1;          // 0..127
    const int q   = tid & 1;           // 16B half of row

    // warp/fragment maps
    const int wid    = tid >> 5;
    const int lane   = tid & 31;
    const int warp_m = (wid & 1) * 64;
    const int warp_n = (wid >> 1) * 32;
    const int lr = lane >> 2;
    const int lc = lane & 3;

    float acc[4][4][4];
    #pragma unroll
    for (int mt = 0; mt < 4; mt++)
        #pragma unroll
        for (int nt = 0; nt < 4; nt++)
            #pragma unroll
            for (int r = 0; r < 4; r++) acc[mt][nt][r] = 0.f;

    auto issue_stage = [&](int s, int k0) {
        uint32_t da = sbase + s * H_ST + row * 48 + q * 16;
        CP_ASYNC16(da, Ag + (size_t)row * K_ + k0 + q * 8);
        uint32_t db = sbase + B_OFF + s * H_ST + row * 48 + q * 16;
        CP_ASYNC16(db, Bg + (size_t)row * K_ + k0 + q * 8);
        CP_COMMIT();
    };

    issue_stage(0, 0);
    issue_stage(1, BKh);

    const __half* smh = (const __half*)smem;
    const int NITER = K_ / BKh;   // 32
    for (int iter = 0; iter < NITER; iter++) {
        const int st = iter & 1;
        CP_WAIT1();
        __syncthreads();

        const __half* As = smh + st * (H_ST / 2);
        const __half* Bs = smh + (B_OFF + st * H_ST) / 2;

        uint32_t af[4][4], bf[4][2];
        #pragma unroll
        for (int mt = 0; mt < 4; mt++) {
            const int r0 = warp_m + mt * 16 + lr;
            af[mt][0] = *(const uint32_t*)(As + r0 * LDH_ + 2 * lc);
            af[mt][1] = *(const uint32_t*)(As + (r0 + 8) * LDH_ + 2 * lc);
            af[mt][2] = *(const uint32_t*)(As + r0 * LDH_ + 2 * lc + 8);
            af[mt][3] = *(const uint32_t*)(As + (r0 + 8) * LDH_ + 2 * lc + 8);
        }
        #pragma unroll
        for (int nt = 0; nt < 4; nt++) {
            const int n0 = warp_n + nt * 8 + lr;
            bf[nt][0] = *(const uint32_t*)(Bs + n0 * LDH_ + 2 * lc);
            bf[nt][1] = *(const uint32_t*)(Bs + n0 * LDH_ + 2 * lc + 8);
        }
        #pragma unroll
        for (int mt = 0; mt < 4; mt++)
            #pragma unroll
            for (int nt = 0; nt < 4; nt++)
                mma_f16(acc[mt][nt][0], acc[mt][nt][1],
                        acc[mt][nt][2], acc[mt][nt][3],
                        af[mt][0], af[mt][1], af[mt][2], af[mt][3],
                        bf[nt][0], bf[nt][1]);

        __syncthreads();
        if (iter + 2 < NITER) issue_stage(st, (iter + 2) * BKh);
        else CP_COMMIT();   // keep wait_group counts consistent
    }

    // epilogue: c0/c1 at (row, 2lc..2lc+1), c2/c3 at (row+8, same)
    #pragma unroll
    for (int mt = 0; mt < 4; mt++) {
        const int r0 = warp_m + mt * 16 + lr;
        #pragma unroll
        for (int nt = 0; nt < 4; nt++) {
            const int cbase = warp_n + nt * 8 + 2 * lc;
            float2 v01 = make_float2(acc[mt][nt][0], acc[mt][nt][1]);
            float2 v23 = make_float2(acc[mt][nt][2], acc[mt][nt][3]);
            *(float2*)(Cg + (size_t)r0 * HW_ + cbase)       = v01;
            *(float2*)(Cg + (size_t)(r0 + 8) * HW_ + cbase) = v23;
        }
    }
}

// ---------------------------------------------------------------------------
// Global average pool (float4 vectorized)
// ---------------------------------------------------------------------------
__global__ __launch_bounds__(256) void pool_kernel(const float* __restrict__ X)
{
    const int bc = blockIdx.x;
    const float4* xp = (const float4*)(X + (size_t)bc * HW_);
    float sum = 0.f;
    for (int i = threadIdx.x; i < HW_ / 4; i += 256) {
        float4 v = xp[i];
        sum += (v.x + v.y) + (v.z + v.w);
    }
    #pragma unroll
    for (int o = 16; o > 0; o >>= 1) sum += __shfl_xor_sync(0xFFFFFFFFu, sum, o);
    __shared__ float sm[8];
    if ((threadIdx.x & 31) == 0) sm[threadIdx.x >> 5] = sum;
    __syncthreads();
    if (threadIdx.x == 0) {
        float t = 0.f;
        #pragma unroll
        for (int i = 0; i < 8; i++) t += sm[i];
        g_pooled[bc] = t * (1.0f / HW_);
    }
}

// ---------------------------------------------------------------------------
// Gate softmax
// ---------------------------------------------------------------------------
__global__ void gate_kernel(const float* __restrict__ Wg, const float* __restrict__ bg)
{
    __shared__ float lg[32];
    const int t = threadIdx.x;
    const int b = t >> 2, i = t & 3;
    float dot = bg[i];
    const float* p = g_pooled + b * C_;
    const float* w = Wg + i * C_;
    for (int c = 0; c < C_; c++) dot += p[c] * w[c];
    lg[t] = dot;
    __syncthreads();
    if (t < B_) {
        float l0 = lg[t*4+0], l1 = lg[t*4+1], l2 = lg[t*4+2], l3 = lg[t*4+3];
        float m = fmaxf(fmaxf(l0, l1), fmaxf(l2, l3));
        float e0 = expf(l0 - m), e1 = expf(l1 - m), e2 = expf(l2 - m), e3 = expf(l3 - m);
        float inv = 1.0f / (e0 + e1 + e2 + e3);
        g_gate[t*4+0] = e0 * inv;
        g_gate[t*4+1] = e1 * inv;
        g_gate[t*4+2] = e2 * inv;
        g_gate[t*4+3] = e3 * inv;
    }
}

// ---------------------------------------------------------------------------
// Dilated 3x3 attention + gate + write out (zero-padding softmax semantics)
// ---------------------------------------------------------------------------
__global__ __launch_bounds__(256) void attn_kernel(float* __restrict__ out)
{
    const int n = blockIdx.x * 256 + threadIdx.x;
    const int dh = blockIdx.y;
    const int b  = blockIdx.z;
    const int i    = dh >> 1;
    const int head = dh & 1;
    const int dil  = 1 << i;
    const int h = n >> 6, w = n & 63;
    const float scale = 0.125f;

    const size_t base = ((size_t)b * M_ + i * 128 + head * 64) * HW_;
    const float* qp = g_qkv + base;
    const float* kp = g_qkv + base + (size_t)C_ * HW_;
    const float* vp = g_qkv + base + (size_t)2 * C_ * HW_;

    float s[9];
    int   nn[9];
    bool  ok[9];

    {
        float q[64];
        #pragma unroll
        for (int c = 0; c < 64; c++) q[c] = qp[(size_t)c * HW_ + n];

        #pragma unroll
        for (int j = 0; j < 9; j++) {
            const int dy = (j / 3 - 1) * dil;
            const int dx = (j % 3 - 1) * dil;
            const int hh = h + dy, ww = w + dx;
            const bool v_ok = ((unsigned)hh < 64u) && ((unsigned)ww < 64u);
            const int nnj = hh * 64 + ww;
            nn[j] = nnj; ok[j] = v_ok;
            float dot = 0.f;
            if (v_ok) {
                const float* kk = kp + nnj;
                #pragma unroll
                for (int c = 0; c < 64; c++) dot += q[c] * kk[(size_t)c * HW_];
            }
            s[j] = dot * scale;
        }
    }

    float m = s[0];
    #pragma unroll
    for (int j = 1; j < 9; j++) m = fmaxf(m, s[j]);
    float sum = 0.f;
    #pragma unroll
    for (int j = 0; j < 9; j++) { s[j] = expf(s[j] - m); sum += s[j]; }
    const float inv = 1.0f / sum;
    #pragma unroll
    for (int j = 0; j < 9; j++) s[j] *= inv;

    float acc[64];
    #pragma unroll
    for (int c = 0; c < 64; c++) acc[c] = 0.f;
    #pragma unroll
    for (int j = 0; j < 9; j++) {
        if (ok[j]) {
            const float p = s[j];
            const float* vv = vp + nn[j];
            #pragma unroll
            for (int c = 0; c < 64; c++) acc[c] += p * vv[(size_t)c * HW_];
        }
    }

    const float g = g_gate[b * 4 + i];
    float* op = out + ((size_t)b * C_ + i * 128 + head * 64) * HW_ + n;
    #pragma unroll
    for (int c = 0; c < 64; c++) op[(size_t)c * HW_] = g * acc[c];
}

// ---------------------------------------------------------------------------
extern "C" void kernel_launch(void* const* d_in, const int* in_sizes, int n_in,
                              void* d_out, int out_size)
{
    const float* x      = (const float*)d_in[0];
    const float* w_qkv  = (const float*)d_in[1];
    const float* w_gate = (const float*)d_in[2];
    const float* b_gate = (const float*)d_in[3];
    float* out = (float*)d_out;

    // convert inputs to half (X transposed to [b][n][k])
    conv_w_kernel<<<(M_ * K_ / 4 + 255) / 256, 256>>>(w_qkv);
    transpose_x_kernel<<<dim3(HW_ / 32, C_ / 32, B_), dim3(32, 8)>>>(x);

    // qkv GEMM (fp16 inputs, fp32 accumulate)
    gemm_qkv_f16<<<dim3(HW_ / 128, M_ / 128, B_), 256, SM_TOT>>>();

    // gate path
    pool_kernel<<<B_ * C_, 256>>>(x);
    gate_kernel<<<1, 32>>>(w_gate, b_gate);

    // attention + gating + output
    attn_kernel<<<dim3(HW_ / 256, 8, B_), 256>>>(out);
}

// round 11
// speedup vs baseline: 1.6378x; 1.0989x over previous
#include <cuda_runtime.h>
#include <cuda_fp16.h>
#include <cstdint>

// ---------------------------------------------------------------------------
// AdaptiveDCA: half-convert (W) + half-transpose (X) -> fp16 mma GEMM
// (ldmatrix + 4-stage cp.async) -> 4x dilated 3x3 attention -> gated concat
// x (8,512,64,64), w_qkv (1536,512), w_gate (4,512), b_gate (4) -> out fp32
// ---------------------------------------------------------------------------

#define B_   8
#define C_   512
#define HW_  4096
#define M_   1536
#define K_   512

__device__ float  g_qkv[(size_t)B_ * M_ * HW_];    // ~201 MB scratch
__device__ __half g_xh[(size_t)B_ * HW_ * K_];     // X^T in half [b][n][k]
__device__ __half g_wh[(size_t)M_ * K_];           // W in half [m][k]
__device__ float  g_pooled[B_ * C_];
__device__ float  g_gate[B_ * 4];

__device__ __forceinline__ uint32_t smem_u32(const void* p) {
    uint32_t a;
    asm("{ .reg .u64 t; cvta.to.shared.u64 t, %1; cvt.u32.u64 %0, t; }"
        : "=r"(a) : "l"(p));
    return a;
}

#define CP_ASYNC16(dst, src) \
    asm volatile("cp.async.cg.shared.global [%0], [%1], 16;" \
                 :: "r"(dst), "l"(src) : "memory")
#define CP_COMMIT() asm volatile("cp.async.commit_group;" ::: "memory")
#define CP_WAIT2()  asm volatile("cp.async.wait_group 2;" ::: "memory")

__device__ __forceinline__ void ldsm_x4(
    uint32_t& r0, uint32_t& r1, uint32_t& r2, uint32_t& r3, uint32_t addr)
{
    asm volatile(
        "ldmatrix.sync.aligned.m8n8.x4.shared.b16 {%0, %1, %2, %3}, [%4];"
        : "=r"(r0), "=r"(r1), "=r"(r2), "=r"(r3) : "r"(addr));
}

__device__ __forceinline__ void mma_f16(
    float& c0, float& c1, float& c2, float& c3,
    uint32_t a0, uint32_t a1, uint32_t a2, uint32_t a3,
    uint32_t b0, uint32_t b1)
{
    asm volatile(
        "mma.sync.aligned.m16n8k16.row.col.f32.f16.f16.f32 "
        "{%0,%1,%2,%3}, {%4,%5,%6,%7}, {%8,%9}, {%0,%1,%2,%3};"
        : "+f"(c0), "+f"(c1), "+f"(c2), "+f"(c3)
        : "r"(a0), "r"(a1), "r"(a2), "r"(a3), "r"(b0), "r"(b1));
}

// ---------------------------------------------------------------------------
// W -> half, [m][k] unchanged layout
// ---------------------------------------------------------------------------
__global__ __launch_bounds__(256) void conv_w_kernel(const float* __restrict__ W)
{
    const int i = blockIdx.x * 256 + threadIdx.x;
    if (i < M_ * K_ / 4) {
        float4 v = ((const float4*)W)[i];
        ((__half2*)g_wh)[i * 2 + 0] = __floats2half2_rn(v.x, v.y);
        ((__half2*)g_wh)[i * 2 + 1] = __floats2half2_rn(v.z, v.w);
    }
}

// ---------------------------------------------------------------------------
// X [b][c][n] -> half transposed [b][n][k=c]; 32x32 smem tiles
// ---------------------------------------------------------------------------
__global__ __launch_bounds__(256) void transpose_x_kernel(const float* __restrict__ X)
{
    __shared__ float sm[32][33];
    const int b  = blockIdx.z;
    const int c0 = blockIdx.y * 32;
    const int n0 = blockIdx.x * 32;
    const int tx = threadIdx.x;
    const int ty = threadIdx.y;

    const float* xp = X + ((size_t)b * C_ + c0) * HW_ + n0;
    #pragma unroll
    for (int i = 0; i < 4; i++)
        sm[ty + 8 * i][tx] = xp[(size_t)(ty + 8 * i) * HW_ + tx];
    __syncthreads();

    __half* op = g_xh + ((size_t)b * HW_ + n0) * K_ + c0;
    #pragma unroll
    for (int i = 0; i < 4; i++)
        op[(size_t)(ty + 8 * i) * K_ + tx] = __float2half_rn(sm[tx][ty + 8 * i]);
}

// ---------------------------------------------------------------------------
// fp16 GEMM: qkv[b,o,n] = sum_c W[o,c] * X[b,c,n]
// BM=128, BN=128, BK=16; 256 threads, 8 warps (2m x 4n), warp tile 64x32.
// Rows padded to 24 halfs (48B): ldmatrix banks (12i+4c) mod 32 distinct.
// 4-stage cp.async ring, wait_group 2, one barrier per iter.
// Stage layout: [stage s]: A at s*12288, B at s*12288+6144. Total 49152 B.
// ---------------------------------------------------------------------------
#define BKh     16
#define LDH_    24                     // halfs per row (48 B)
#define TILE_B  6144                   // one 128-row tile (48B * 128)
#define STG_B   (2 * TILE_B)           // 12288 per stage (A + B)
#define SM_TOT  (4 * STG_B)            // 49152 (= default smem cap)

__global__ __launch_bounds__(256) void gemm_qkv_f16()
{
    extern __shared__ uint8_t smem[];
    const uint32_t sbase = smem_u32(smem);

    const int tid = threadIdx.x;
    const int bz  = blockIdx.z;
    const int bm0 = blockIdx.y * 128;
    const int bn0 = blockIdx.x * 128;

    const __half* Ag = g_wh + (size_t)bm0 * K_;                 // [m][k]
    const __half* Bg = g_xh + ((size_t)bz * HW_ + bn0) * K_;    // [n][k]
    float* Cg = g_qkv + ((size_t)bz * M_ + bm0) * HW_ + bn0;

    // cp.async: 1 A-chunk + 1 B-chunk per thread (16B each)
    const int row = tid >> 1;          // 0..127
    const int q   = tid & 1;           // 16B half of 32B row

    // warp/fragment maps
    const int wid    = tid >> 5;
    const int lane   = tid & 31;
    const int warp_m = (wid & 1) * 64;
    const int warp_n = (wid >> 1) * 32;
    const int lrow   = lane & 15;      // ldmatrix row-within-16
    const int lchunk = lane >> 4;      // ldmatrix 16B chunk (k half)

    float acc[4][4][4];
    #pragma unroll
    for (int mt = 0; mt < 4; mt++)
        #pragma unroll
        for (int nt = 0; nt < 4; nt++)
            #pragma unroll
            for (int r = 0; r < 4; r++) acc[mt][nt][r] = 0.f;

    auto issue_stage = [&](int s, int k0) {
        uint32_t da = sbase + s * STG_B + row * 48 + q * 16;
        CP_ASYNC16(da, Ag + (size_t)row * K_ + k0 + q * 8);
        uint32_t db = da + TILE_B;
        CP_ASYNC16(db, Bg + (size_t)row * K_ + k0 + q * 8);
        CP_COMMIT();
    };

    issue_stage(0, 0);
    issue_stage(1, BKh);
    issue_stage(2, 2 * BKh);

    const int NITER = K_ / BKh;   // 32
    for (int iter = 0; iter < NITER; iter++) {
        const int st = iter & 3;
        CP_WAIT2();                // own copies for stage `st` complete
        __syncthreads();           // publish; also fences last iter's reads

        if (iter + 3 < NITER) issue_stage((iter + 3) & 3, (iter + 3) * BKh);
        else CP_COMMIT();          // keep pending-group count constant

        const uint32_t Ab = sbase + st * STG_B;
        const uint32_t Bb = Ab + TILE_B;

        uint32_t af[4][4], bf[4][2];
        #pragma unroll
        for (int mt = 0; mt < 4; mt++)
            ldsm_x4(af[mt][0], af[mt][1], af[mt][2], af[mt][3],
                    Ab + (warp_m + mt * 16 + lrow) * 48 + lchunk * 16);
        #pragma unroll
        for (int p = 0; p < 2; p++)
            ldsm_x4(bf[2 * p][0], bf[2 * p + 1][0], bf[2 * p][1], bf[2 * p + 1][1],
                    Bb + (warp_n + p * 16 + lrow) * 48 + lchunk * 16);

        #pragma unroll
        for (int mt = 0; mt < 4; mt++)
            #pragma unroll
            for (int nt = 0; nt < 4; nt++)
                mma_f16(acc[mt][nt][0], acc[mt][nt][1],
                        acc[mt][nt][2], acc[mt][nt][3],
                        af[mt][0], af[mt][1], af[mt][2], af[mt][3],
                        bf[nt][0], bf[nt][1]);
    }

    // epilogue: c0/c1 at (row, 2lc), c2/c3 at (row+8, 2lc)
    const int lr = lane >> 2;
    const int lc = lane & 3;
    #pragma unroll
    for (int mt = 0; mt < 4; mt++) {
        const int r0 = warp_m + mt * 16 + lr;
        #pragma unroll
        for (int nt = 0; nt < 4; nt++) {
            const int cbase = warp_n + nt * 8 + 2 * lc;
            float2 v01 = make_float2(acc[mt][nt][0], acc[mt][nt][1]);
            float2 v23 = make_float2(acc[mt][nt][2], acc[mt][nt][3]);
            *(float2*)(Cg + (size_t)r0 * HW_ + cbase)       = v01;
            *(float2*)(Cg + (size_t)(r0 + 8) * HW_ + cbase) = v23;
        }
    }
}

// ---------------------------------------------------------------------------
// Global average pool (float4 vectorized)
// ---------------------------------------------------------------------------
__global__ __launch_bounds__(256) void pool_kernel(const float* __restrict__ X)
{
    const int bc = blockIdx.x;
    const float4* xp = (const float4*)(X + (size_t)bc * HW_);
    float sum = 0.f;
    for (int i = threadIdx.x; i < HW_ / 4; i += 256) {
        float4 v = xp[i];
        sum += (v.x + v.y) + (v.z + v.w);
    }
    #pragma unroll
    for (int o = 16; o > 0; o >>= 1) sum += __shfl_xor_sync(0xFFFFFFFFu, sum, o);
    __shared__ float sm[8];
    if ((threadIdx.x & 31) == 0) sm[threadIdx.x >> 5] = sum;
    __syncthreads();
    if (threadIdx.x == 0) {
        float t = 0.f;
        #pragma unroll
        for (int i = 0; i < 8; i++) t += sm[i];
        g_pooled[bc] = t * (1.0f / HW_);
    }
}

// ---------------------------------------------------------------------------
// Gate softmax
// ---------------------------------------------------------------------------
__global__ void gate_kernel(const float* __restrict__ Wg, const float* __restrict__ bg)
{
    __shared__ float lg[32];
    const int t = threadIdx.x;
    const int b = t >> 2, i = t & 3;
    float dot = bg[i];
    const float* p = g_pooled + b * C_;
    const float* w = Wg + i * C_;
    for (int c = 0; c < C_; c++) dot += p[c] * w[c];
    lg[t] = dot;
    __syncthreads();
    if (t < B_) {
        float l0 = lg[t*4+0], l1 = lg[t*4+1], l2 = lg[t*4+2], l3 = lg[t*4+3];
        float m = fmaxf(fmaxf(l0, l1), fmaxf(l2, l3));
        float e0 = expf(l0 - m), e1 = expf(l1 - m), e2 = expf(l2 - m), e3 = expf(l3 - m);
        float inv = 1.0f / (e0 + e1 + e2 + e3);
        g_gate[t*4+0] = e0 * inv;
        g_gate[t*4+1] = e1 * inv;
        g_gate[t*4+2] = e2 * inv;
        g_gate[t*4+3] = e3 * inv;
    }
}

// ---------------------------------------------------------------------------
// Dilated 3x3 attention + gate + write out (zero-padding softmax semantics)
// ---------------------------------------------------------------------------
__global__ __launch_bounds__(256) void attn_kernel(float* __restrict__ out)
{
    const int n = blockIdx.x * 256 + threadIdx.x;
    const int dh = blockIdx.y;
    const int b  = blockIdx.z;
    const int i    = dh >> 1;
    const int head = dh & 1;
    const int dil  = 1 << i;
    const int h = n >> 6, w = n & 63;
    const float scale = 0.125f;

    const size_t base = ((size_t)b * M_ + i * 128 + head * 64) * HW_;
    const float* qp = g_qkv + base;
    const float* kp = g_qkv + base + (size_t)C_ * HW_;
    const float* vp = g_qkv + base + (size_t)2 * C_ * HW_;

    float s[9];
    int   nn[9];
    bool  ok[9];

    {
        float q[64];
        #pragma unroll
        for (int c = 0; c < 64; c++) q[c] = qp[(size_t)c * HW_ + n];

        #pragma unroll
        for (int j = 0; j < 9; j++) {
            const int dy = (j / 3 - 1) * dil;
            const int dx = (j % 3 - 1) * dil;
            const int hh = h + dy, ww = w + dx;
            const bool v_ok = ((unsigned)hh < 64u) && ((unsigned)ww < 64u);
            const int nnj = hh * 64 + ww;
            nn[j] = nnj; ok[j] = v_ok;
            float dot = 0.f;
            if (v_ok) {
                const float* kk = kp + nnj;
                #pragma unroll
                for (int c = 0; c < 64; c++) dot += q[c] * kk[(size_t)c * HW_];
            }
            s[j] = dot * scale;
        }
    }

    float m = s[0];
    #pragma unroll
    for (int j = 1; j < 9; j++) m = fmaxf(m, s[j]);
    float sum = 0.f;
    #pragma unroll
    for (int j = 0; j < 9; j++) { s[j] = expf(s[j] - m); sum += s[j]; }
    const float inv = 1.0f / sum;
    #pragma unroll
    for (int j = 0; j < 9; j++) s[j] *= inv;

    float acc[64];
    #pragma unroll
    for (int c = 0; c < 64; c++) acc[c] = 0.f;
    #pragma unroll
    for (int j = 0; j < 9; j++) {
        if (ok[j]) {
            const float p = s[j];
            const float* vv = vp + nn[j];
            #pragma unroll
            for (int c = 0; c < 64; c++) acc[c] += p * vv[(size_t)c * HW_];
        }
    }

    const float g = g_gate[b * 4 + i];
    float* op = out + ((size_t)b * C_ + i * 128 + head * 64) * HW_ + n;
    #pragma unroll
    for (int c = 0; c < 64; c++) op[(size_t)c * HW_] = g * acc[c];
}

// ---------------------------------------------------------------------------
extern "C" void kernel_launch(void* const* d_in, const int* in_sizes, int n_in,
                              void* d_out, int out_size)
{
    const float* x      = (const float*)d_in[0];
    const float* w_qkv  = (const float*)d_in[1];
    const float* w_gate = (const float*)d_in[2];
    const float* b_gate = (const float*)d_in[3];
    float* out = (float*)d_out;

    // convert inputs to half (X transposed to [b][n][k])
    conv_w_kernel<<<(M_ * K_ / 4 + 255) / 256, 256>>>(w_qkv);
    transpose_x_kernel<<<dim3(HW_ / 32, C_ / 32, B_), dim3(32, 8)>>>(x);

    // qkv GEMM (fp16 inputs, fp32 accumulate)
    gemm_qkv_f16<<<dim3(HW_ / 128, M_ / 128, B_), 256, SM_TOT>>>();

    // gate path
    pool_kernel<<<B_ * C_, 256>>>(x);
    gate_kernel<<<1, 32>>>(w_gate, b_gate);

    // attention + gating + output
    attn_kernel<<<dim3(HW_ / 256, 8, B_), 256>>>(out);
}

// round 13
// speedup vs baseline: 1.7433x; 1.0644x over previous
#include <cuda_runtime.h>
#include <cuda_fp16.h>
#include <cstdint>

// ---------------------------------------------------------------------------
// AdaptiveDCA: conv_w (+zero pooled) -> transpose_x (+fused pool) ->
// fp16 mma GEMM (ldmatrix + 4-stage cp.async) -> channel-split attention
// x (8,512,64,64), w_qkv (1536,512), w_gate (4,512), b_gate (4) -> out fp32
// ---------------------------------------------------------------------------

#define B_   8
#define C_   512
#define HW_  4096
#define M_   1536
#define K_   512

__device__ float  g_qkv[(size_t)B_ * M_ * HW_];    // ~201 MB scratch
__device__ __half g_xh[(size_t)B_ * HW_ * K_];     // X^T in half [b][n][k]
__device__ __half g_wh[(size_t)M_ * K_];           // W in half [m][k]
__device__ float  g_pooled[B_ * C_];               // SUM over n (scaled in gate)
__device__ float  g_gate[B_ * 4];

__device__ __forceinline__ uint32_t smem_u32(const void* p) {
    uint32_t a;
    asm("{ .reg .u64 t; cvta.to.shared.u64 t, %1; cvt.u32.u64 %0, t; }"
        : "=r"(a) : "l"(p));
    return a;
}

#define CP_ASYNC16(dst, src) \
    asm volatile("cp.async.cg.shared.global [%0], [%1], 16;" \
                 :: "r"(dst), "l"(src) : "memory")
#define CP_COMMIT() asm volatile("cp.async.commit_group;" ::: "memory")
#define CP_WAIT2()  asm volatile("cp.async.wait_group 2;" ::: "memory")

__device__ __forceinline__ void ldsm_x4(
    uint32_t& r0, uint32_t& r1, uint32_t& r2, uint32_t& r3, uint32_t addr)
{
    asm volatile(
        "ldmatrix.sync.aligned.m8n8.x4.shared.b16 {%0, %1, %2, %3}, [%4];"
        : "=r"(r0), "=r"(r1), "=r"(r2), "=r"(r3) : "r"(addr));
}

__device__ __forceinline__ void mma_f16(
    float& c0, float& c1, float& c2, float& c3,
    uint32_t a0, uint32_t a1, uint32_t a2, uint32_t a3,
    uint32_t b0, uint32_t b1)
{
    asm volatile(
        "mma.sync.aligned.m16n8k16.row.col.f32.f16.f16.f32 "
        "{%0,%1,%2,%3}, {%4,%5,%6,%7}, {%8,%9}, {%0,%1,%2,%3};"
        : "+f"(c0), "+f"(c1), "+f"(c2), "+f"(c3)
        : "r"(a0), "r"(a1), "r"(a2), "r"(a3), "r"(b0), "r"(b1));
}

// ---------------------------------------------------------------------------
// W -> half [m][k]; also zeroes g_pooled (runs before transpose_x's atomics)
// ---------------------------------------------------------------------------
__global__ __launch_bounds__(256) void conv_w_kernel(const float* __restrict__ W)
{
    const int i = blockIdx.x * 256 + threadIdx.x;
    if (i < B_ * C_) g_pooled[i] = 0.f;
    if (i < M_ * K_ / 4) {
        float4 v = ((const float4*)W)[i];
        ((__half2*)g_wh)[i * 2 + 0] = __floats2half2_rn(v.x, v.y);
        ((__half2*)g_wh)[i * 2 + 1] = __floats2half2_rn(v.z, v.w);
    }
}

// ---------------------------------------------------------------------------
// X [b][c][n] -> half transposed [b][n][k=c]; 32x32 smem tiles.
// Fused global-average-pool partials: per-channel tile sums atomicAdd'ed
// into g_pooled (sum over n; gate applies 1/HW).
// ---------------------------------------------------------------------------
__global__ __launch_bounds__(256) void transpose_x_kernel(const float* __restrict__ X)
{
    __shared__ float sm[32][33];
    const int b  = blockIdx.z;
    const int c0 = blockIdx.y * 32;
    const int n0 = blockIdx.x * 32;
    const int tid = threadIdx.y * 32 + threadIdx.x;
    const int tx = threadIdx.x;
    const int ty = threadIdx.y;

    const float* xp = X + ((size_t)b * C_ + c0) * HW_ + n0;
    #pragma unroll
    for (int i = 0; i < 4; i++)
        sm[ty + 8 * i][tx] = xp[(size_t)(ty + 8 * i) * HW_ + tx];
    __syncthreads();

    // transposed half write
    __half* op = g_xh + ((size_t)b * HW_ + n0) * K_ + c0;
    #pragma unroll
    for (int i = 0; i < 4; i++)
        op[(size_t)(ty + 8 * i) * K_ + tx] = __float2half_rn(sm[tx][ty + 8 * i]);

    // fused pool: 8 lanes per channel, shfl-reduce, one atomic per channel
    {
        const int cl = tid >> 3;          // 0..31 channel-local
        const int j  = tid & 7;           // 0..7
        float p = sm[cl][j * 4 + 0] + sm[cl][j * 4 + 1] +
                  sm[cl][j * 4 + 2] + sm[cl][j * 4 + 3];
        p += __shfl_xor_sync(0xFFFFFFFFu, p, 1);
        p += __shfl_xor_sync(0xFFFFFFFFu, p, 2);
        p += __shfl_xor_sync(0xFFFFFFFFu, p, 4);
        if (j == 0) atomicAdd(&g_pooled[b * C_ + c0 + cl], p);
    }
}

// ---------------------------------------------------------------------------
// fp16 GEMM: qkv[b,o,n] = sum_c W[o,c] * X[b,c,n]
// BM=128, BN=128, BK=16; 8 warps (2m x 4n), warp tile 64x32; ldmatrix;
// 4-stage cp.async ring, wait_group 2, one barrier per iter. SMEM 49152 B.
// ---------------------------------------------------------------------------
#define BKh     16
#define LDH_    24                     // halfs per row (48 B)
#define TILE_B  6144
#define STG_B   (2 * TILE_B)
#define SM_TOT  (4 * STG_B)            // 49152

__global__ __launch_bounds__(256) void gemm_qkv_f16()
{
    extern __shared__ uint8_t smem[];
    const uint32_t sbase = smem_u32(smem);

    const int tid = threadIdx.x;
    const int bz  = blockIdx.z;
    const int bm0 = blockIdx.y * 128;
    const int bn0 = blockIdx.x * 128;

    const __half* Ag = g_wh + (size_t)bm0 * K_;
    const __half* Bg = g_xh + ((size_t)bz * HW_ + bn0) * K_;
    float* Cg = g_qkv + ((size_t)bz * M_ + bm0) * HW_ + bn0;

    const int row = tid >> 1;
    const int q   = tid & 1;

    const int wid    = tid >> 5;
    const int lane   = tid & 31;
    const int warp_m = (wid & 1) * 64;
    const int warp_n = (wid >> 1) * 32;
    const int lrow   = lane & 15;
    const int lchunk = lane >> 4;

    float acc[4][4][4];
    #pragma unroll
    for (int mt = 0; mt < 4; mt++)
        #pragma unroll
        for (int nt = 0; nt < 4; nt++)
            #pragma unroll
            for (int r = 0; r < 4; r++) acc[mt][nt][r] = 0.f;

    auto issue_stage = [&](int s, int k0) {
        uint32_t da = sbase + s * STG_B + row * 48 + q * 16;
        CP_ASYNC16(da, Ag + (size_t)row * K_ + k0 + q * 8);
        CP_ASYNC16(da + TILE_B, Bg + (size_t)row * K_ + k0 + q * 8);
        CP_COMMIT();
    };

    issue_stage(0, 0);
    issue_stage(1, BKh);
    issue_stage(2, 2 * BKh);

    const int NITER = K_ / BKh;   // 32
    for (int iter = 0; iter < NITER; iter++) {
        const int st = iter & 3;
        CP_WAIT2();
        __syncthreads();

        if (iter + 3 < NITER) issue_stage((iter + 3) & 3, (iter + 3) * BKh);
        else CP_COMMIT();

        const uint32_t Ab = sbase + st * STG_B;
        const uint32_t Bb = Ab + TILE_B;

        uint32_t af[4][4], bf[4][2];
        #pragma unroll
        for (int mt = 0; mt < 4; mt++)
            ldsm_x4(af[mt][0], af[mt][1], af[mt][2], af[mt][3],
                    Ab + (warp_m + mt * 16 + lrow) * 48 + lchunk * 16);
        #pragma unroll
        for (int p = 0; p < 2; p++)
            ldsm_x4(bf[2 * p][0], bf[2 * p + 1][0], bf[2 * p][1], bf[2 * p + 1][1],
                    Bb + (warp_n + p * 16 + lrow) * 48 + lchunk * 16);

        #pragma unroll
        for (int mt = 0; mt < 4; mt++)
            #pragma unroll
            for (int nt = 0; nt < 4; nt++)
                mma_f16(acc[mt][nt][0], acc[mt][nt][1],
                        acc[mt][nt][2], acc[mt][nt][3],
                        af[mt][0], af[mt][1], af[mt][2], af[mt][3],
                        bf[nt][0], bf[nt][1]);
    }

    const int lr = lane >> 2;
    const int lc = lane & 3;
    #pragma unroll
    for (int mt = 0; mt < 4; mt++) {
        const int r0 = warp_m + mt * 16 + lr;
        #pragma unroll
        for (int nt = 0; nt < 4; nt++) {
            const int cbase = warp_n + nt * 8 + 2 * lc;
            float2 v01 = make_float2(acc[mt][nt][0], acc[mt][nt][1]);
            float2 v23 = make_float2(acc[mt][nt][2], acc[mt][nt][3]);
            *(float2*)(Cg + (size_t)r0 * HW_ + cbase)       = v01;
            *(float2*)(Cg + (size_t)(r0 + 8) * HW_ + cbase) = v23;
        }
    }
}

// ---------------------------------------------------------------------------
// Gate softmax (g_pooled holds SUM over n; apply 1/HW here)
// ---------------------------------------------------------------------------
__global__ void gate_kernel(const float* __restrict__ Wg, const float* __restrict__ bg)
{
    __shared__ float lg[32];
    const int t = threadIdx.x;
    const int b = t >> 2, i = t & 3;
    float dot = 0.f;
    const float* p = g_pooled + b * C_;
    const float* w = Wg + i * C_;
    for (int c = 0; c < C_; c++) dot += p[c] * w[c];
    lg[t] = dot * (1.0f / HW_) + bg[i];
    __syncthreads();
    if (t < B_) {
        float l0 = lg[t*4+0], l1 = lg[t*4+1], l2 = lg[t*4+2], l3 = lg[t*4+3];
        float m = fmaxf(fmaxf(l0, l1), fmaxf(l2, l3));
        float e0 = expf(l0 - m), e1 = expf(l1 - m), e2 = expf(l2 - m), e3 = expf(l3 - m);
        float inv = 1.0f / (e0 + e1 + e2 + e3);
        g_gate[t*4+0] = e0 * inv;
        g_gate[t*4+1] = e1 * inv;
        g_gate[t*4+2] = e2 * inv;
        g_gate[t*4+3] = e3 * inv;
    }
}

// ---------------------------------------------------------------------------
// Dilated 3x3 attention, channel-split 2-way: thread pair (t, t^1) shares a
// position; each holds 32 of the 64 head channels. Logits completed via
// shfl_xor(1). Zero-padding softmax semantics preserved.
// ---------------------------------------------------------------------------
__global__ __launch_bounds__(256) void attn_kernel(float* __restrict__ out)
{
    const int t    = threadIdx.x;
    const int half = t & 1;                          // channel half
    const int n    = blockIdx.x * 128 + (t >> 1);    // position
    const int dh = blockIdx.y;
    const int b  = blockIdx.z;
    const int i    = dh >> 1;
    const int head = dh & 1;
    const int dil  = 1 << i;
    const int h = n >> 6, w = n & 63;
    const float scale = 0.125f;

    const int ch0 = i * 128 + head * 64 + half * 32;
    const size_t base = ((size_t)b * M_ + ch0) * HW_;
    const float* qp = g_qkv + base;
    const float* kp = g_qkv + base + (size_t)C_ * HW_;
    const float* vp = g_qkv + base + (size_t)2 * C_ * HW_;

    float s[9];
    int   nn[9];
    bool  ok[9];

    {
        float q[32];
        #pragma unroll
        for (int c = 0; c < 32; c++) q[c] = qp[(size_t)c * HW_ + n];

        #pragma unroll
        for (int j = 0; j < 9; j++) {
            const int dy = (j / 3 - 1) * dil;
            const int dx = (j % 3 - 1) * dil;
            const int hh = h + dy, ww = w + dx;
            const bool v_ok = ((unsigned)hh < 64u) && ((unsigned)ww < 64u);
            const int nnj = hh * 64 + ww;
            nn[j] = nnj; ok[j] = v_ok;
            float dot = 0.f;
            if (v_ok) {
                const float* kk = kp + nnj;
                #pragma unroll
                for (int c = 0; c < 32; c++) dot += q[c] * kk[(size_t)c * HW_];
            }
            // complete the 64-ch dot across the pair (uniform: pair shares n)
            dot += __shfl_xor_sync(0xFFFFFFFFu, dot, 1);
            s[j] = dot * scale;
        }
    }

    float m = s[0];
    #pragma unroll
    for (int j = 1; j < 9; j++) m = fmaxf(m, s[j]);
    float sum = 0.f;
    #pragma unroll
    for (int j = 0; j < 9; j++) { s[j] = expf(s[j] - m); sum += s[j]; }
    const float inv = 1.0f / sum;
    #pragma unroll
    for (int j = 0; j < 9; j++) s[j] *= inv;

    float acc[32];
    #pragma unroll
    for (int c = 0; c < 32; c++) acc[c] = 0.f;
    #pragma unroll
    for (int j = 0; j < 9; j++) {
        if (ok[j]) {
            const float p = s[j];
            const float* vv = vp + nn[j];
            #pragma unroll
            for (int c = 0; c < 32; c++) acc[c] += p * vv[(size_t)c * HW_];
        }
    }

    const float g = g_gate[b * 4 + i];
    float* op = out + ((size_t)b * C_ + ch0) * HW_ + n;
    #pragma unroll
    for (int c = 0; c < 32; c++) op[(size_t)c * HW_] = g * acc[c];
}

// ---------------------------------------------------------------------------
extern "C" void kernel_launch(void* const* d_in, const int* in_sizes, int n_in,
                              void* d_out, int out_size)
{
    const float* x      = (const float*)d_in[0];
    const float* w_qkv  = (const float*)d_in[1];
    const float* w_gate = (const float*)d_in[2];
    const float* b_gate = (const float*)d_in[3];
    float* out = (float*)d_out;

    // W -> half (+ zero pooled), X -> half transposed (+ fused pool partials)
    conv_w_kernel<<<(M_ * K_ / 4 + 255) / 256, 256>>>(w_qkv);
    transpose_x_kernel<<<dim3(HW_ / 32, C_ / 32, B_), dim3(32, 8)>>>(x);

    // qkv GEMM (fp16 inputs, fp32 accumulate)
    gemm_qkv_f16<<<dim3(HW_ / 128, M_ / 128, B_), 256, SM_TOT>>>();

    // gate
    gate_kernel<<<1, 32>>>(w_gate, b_gate);

    // attention + gating + output (2 threads per position)
    attn_kernel<<<dim3(HW_ / 128, 8, B_), 256>>>(out);
}

// round 14
// speedup vs baseline: 1.8024x; 1.0339x over previous
#include <cuda_runtime.h>
#include <cuda_fp16.h>
#include <cstdint>

// ---------------------------------------------------------------------------
// AdaptiveDCA: conv_w (+zero pooled) -> transpose_x (+fused pool) ->
// fp16 mma GEMM (ldmatrix + 4-stage cp.async, fp16 C) -> channel-split attn
// x (8,512,64,64), w_qkv (1536,512), w_gate (4,512), b_gate (4) -> out fp32
// qkv scratch held in fp16 (halves GEMM C-write + attn read traffic).
// ---------------------------------------------------------------------------

#define B_   8
#define C_   512
#define HW_  4096
#define M_   1536
#define K_   512

__device__ __half g_qkv[(size_t)B_ * M_ * HW_];    // ~100 MB scratch (fp16)
__device__ __half g_xh[(size_t)B_ * HW_ * K_];     // X^T in half [b][n][k]
__device__ __half g_wh[(size_t)M_ * K_];           // W in half [m][k]
__device__ float  g_pooled[B_ * C_];               // SUM over n (scaled in gate)
__device__ float  g_gate[B_ * 4];

__device__ __forceinline__ uint32_t smem_u32(const void* p) {
    uint32_t a;
    asm("{ .reg .u64 t; cvta.to.shared.u64 t, %1; cvt.u32.u64 %0, t; }"
        : "=r"(a) : "l"(p));
    return a;
}

#define CP_ASYNC16(dst, src) \
    asm volatile("cp.async.cg.shared.global [%0], [%1], 16;" \
                 :: "r"(dst), "l"(src) : "memory")
#define CP_COMMIT() asm volatile("cp.async.commit_group;" ::: "memory")
#define CP_WAIT2()  asm volatile("cp.async.wait_group 2;" ::: "memory")

__device__ __forceinline__ void ldsm_x4(
    uint32_t& r0, uint32_t& r1, uint32_t& r2, uint32_t& r3, uint32_t addr)
{
    asm volatile(
        "ldmatrix.sync.aligned.m8n8.x4.shared.b16 {%0, %1, %2, %3}, [%4];"
        : "=r"(r0), "=r"(r1), "=r"(r2), "=r"(r3) : "r"(addr));
}

__device__ __forceinline__ void mma_f16(
    float& c0, float& c1, float& c2, float& c3,
    uint32_t a0, uint32_t a1, uint32_t a2, uint32_t a3,
    uint32_t b0, uint32_t b1)
{
    asm volatile(
        "mma.sync.aligned.m16n8k16.row.col.f32.f16.f16.f32 "
        "{%0,%1,%2,%3}, {%4,%5,%6,%7}, {%8,%9}, {%0,%1,%2,%3};"
        : "+f"(c0), "+f"(c1), "+f"(c2), "+f"(c3)
        : "r"(a0), "r"(a1), "r"(a2), "r"(a3), "r"(b0), "r"(b1));
}

// ---------------------------------------------------------------------------
// W -> half [m][k]; also zeroes g_pooled (runs before transpose_x's atomics)
// ---------------------------------------------------------------------------
__global__ __launch_bounds__(256) void conv_w_kernel(const float* __restrict__ W)
{
    const int i = blockIdx.x * 256 + threadIdx.x;
    if (i < B_ * C_) g_pooled[i] = 0.f;
    if (i < M_ * K_ / 4) {
        float4 v = ((const float4*)W)[i];
        ((__half2*)g_wh)[i * 2 + 0] = __floats2half2_rn(v.x, v.y);
        ((__half2*)g_wh)[i * 2 + 1] = __floats2half2_rn(v.z, v.w);
    }
}

// ---------------------------------------------------------------------------
// X [b][c][n] -> half transposed [b][n][k=c]; 32x32 smem tiles.
// Fused global-average-pool partials (sum over n; gate applies 1/HW).
// ---------------------------------------------------------------------------
__global__ __launch_bounds__(256) void transpose_x_kernel(const float* __restrict__ X)
{
    __shared__ float sm[32][33];
    const int b  = blockIdx.z;
    const int c0 = blockIdx.y * 32;
    const int n0 = blockIdx.x * 32;
    const int tid = threadIdx.y * 32 + threadIdx.x;
    const int tx = threadIdx.x;
    const int ty = threadIdx.y;

    const float* xp = X + ((size_t)b * C_ + c0) * HW_ + n0;
    #pragma unroll
    for (int i = 0; i < 4; i++)
        sm[ty + 8 * i][tx] = xp[(size_t)(ty + 8 * i) * HW_ + tx];
    __syncthreads();

    __half* op = g_xh + ((size_t)b * HW_ + n0) * K_ + c0;
    #pragma unroll
    for (int i = 0; i < 4; i++)
        op[(size_t)(ty + 8 * i) * K_ + tx] = __float2half_rn(sm[tx][ty + 8 * i]);

    {
        const int cl = tid >> 3;
        const int j  = tid & 7;
        float p = sm[cl][j * 4 + 0] + sm[cl][j * 4 + 1] +
                  sm[cl][j * 4 + 2] + sm[cl][j * 4 + 3];
        p += __shfl_xor_sync(0xFFFFFFFFu, p, 1);
        p += __shfl_xor_sync(0xFFFFFFFFu, p, 2);
        p += __shfl_xor_sync(0xFFFFFFFFu, p, 4);
        if (j == 0) atomicAdd(&g_pooled[b * C_ + c0 + cl], p);
    }
}

// ---------------------------------------------------------------------------
// fp16 GEMM: qkv[b,o,n] = sum_c W[o,c] * X[b,c,n]; fp16 C output.
// BM=128, BN=128, BK=16; 8 warps (2m x 4n), warp tile 64x32; ldmatrix;
// 4-stage cp.async ring, wait_group 2, one barrier per iter. SMEM 49152 B.
// ---------------------------------------------------------------------------
#define BKh     16
#define LDH_    24
#define TILE_B  6144
#define STG_B   (2 * TILE_B)
#define SM_TOT  (4 * STG_B)            // 49152

__global__ __launch_bounds__(256) void gemm_qkv_f16()
{
    extern __shared__ uint8_t smem[];
    const uint32_t sbase = smem_u32(smem);

    const int tid = threadIdx.x;
    const int bz  = blockIdx.z;
    const int bm0 = blockIdx.y * 128;
    const int bn0 = blockIdx.x * 128;

    const __half* Ag = g_wh + (size_t)bm0 * K_;
    const __half* Bg = g_xh + ((size_t)bz * HW_ + bn0) * K_;
    __half* Cg = g_qkv + ((size_t)bz * M_ + bm0) * HW_ + bn0;

    const int row = tid >> 1;
    const int q   = tid & 1;

    const int wid    = tid >> 5;
    const int lane   = tid & 31;
    const int warp_m = (wid & 1) * 64;
    const int warp_n = (wid >> 1) * 32;
    const int lrow   = lane & 15;
    const int lchunk = lane >> 4;

    float acc[4][4][4];
    #pragma unroll
    for (int mt = 0; mt < 4; mt++)
        #pragma unroll
        for (int nt = 0; nt < 4; nt++)
            #pragma unroll
            for (int r = 0; r < 4; r++) acc[mt][nt][r] = 0.f;

    auto issue_stage = [&](int s, int k0) {
        uint32_t da = sbase + s * STG_B + row * 48 + q * 16;
        CP_ASYNC16(da, Ag + (size_t)row * K_ + k0 + q * 8);
        CP_ASYNC16(da + TILE_B, Bg + (size_t)row * K_ + k0 + q * 8);
        CP_COMMIT();
    };

    issue_stage(0, 0);
    issue_stage(1, BKh);
    issue_stage(2, 2 * BKh);

    const int NITER = K_ / BKh;   // 32
    for (int iter = 0; iter < NITER; iter++) {
        const int st = iter & 3;
        CP_WAIT2();
        __syncthreads();

        if (iter + 3 < NITER) issue_stage((iter + 3) & 3, (iter + 3) * BKh);
        else CP_COMMIT();

        const uint32_t Ab = sbase + st * STG_B;
        const uint32_t Bb = Ab + TILE_B;

        uint32_t af[4][4], bf[4][2];
        #pragma unroll
        for (int mt = 0; mt < 4; mt++)
            ldsm_x4(af[mt][0], af[mt][1], af[mt][2], af[mt][3],
                    Ab + (warp_m + mt * 16 + lrow) * 48 + lchunk * 16);
        #pragma unroll
        for (int p = 0; p < 2; p++)
            ldsm_x4(bf[2 * p][0], bf[2 * p + 1][0], bf[2 * p][1], bf[2 * p + 1][1],
                    Bb + (warp_n + p * 16 + lrow) * 48 + lchunk * 16);

        #pragma unroll
        for (int mt = 0; mt < 4; mt++)
            #pragma unroll
            for (int nt = 0; nt < 4; nt++)
                mma_f16(acc[mt][nt][0], acc[mt][nt][1],
                        acc[mt][nt][2], acc[mt][nt][3],
                        af[mt][0], af[mt][1], af[mt][2], af[mt][3],
                        bf[nt][0], bf[nt][1]);
    }

    // epilogue: fp16 C. c0/c1 -> (row, 2lc), c2/c3 -> (row+8, 2lc)
    const int lr = lane >> 2;
    const int lc = lane & 3;
    #pragma unroll
    for (int mt = 0; mt < 4; mt++) {
        const int r0 = warp_m + mt * 16 + lr;
        #pragma unroll
        for (int nt = 0; nt < 4; nt++) {
            const int cbase = warp_n + nt * 8 + 2 * lc;
            __half2 v01 = __floats2half2_rn(acc[mt][nt][0], acc[mt][nt][1]);
            __half2 v23 = __floats2half2_rn(acc[mt][nt][2], acc[mt][nt][3]);
            *(__half2*)(Cg + (size_t)r0 * HW_ + cbase)       = v01;
            *(__half2*)(Cg + (size_t)(r0 + 8) * HW_ + cbase) = v23;
        }
    }
}

// ---------------------------------------------------------------------------
// Gate softmax, parallel: 32 warps, warp w -> (b = w/4, i = w%4) dot product.
// g_pooled holds SUM over n; apply 1/HW here.
// ---------------------------------------------------------------------------
__global__ __launch_bounds__(1024) void gate_kernel(
    const float* __restrict__ Wg, const float* __restrict__ bg)
{
    __shared__ float lg[32];
    const int warp = threadIdx.x >> 5;
    const int lane = threadIdx.x & 31;
    const int b = warp >> 2, i = warp & 3;

    const float* p = g_pooled + b * C_;
    const float* w = Wg + i * C_;
    float dot = 0.f;
    for (int c = lane; c < C_; c += 32) dot += p[c] * w[c];
    #pragma unroll
    for (int o = 16; o > 0; o >>= 1) dot += __shfl_xor_sync(0xFFFFFFFFu, dot, o);
    if (lane == 0) lg[warp] = dot * (1.0f / HW_) + bg[i];
    __syncthreads();

    if (threadIdx.x < B_) {
        const int t = threadIdx.x;
        float l0 = lg[t*4+0], l1 = lg[t*4+1], l2 = lg[t*4+2], l3 = lg[t*4+3];
        float m = fmaxf(fmaxf(l0, l1), fmaxf(l2, l3));
        float e0 = expf(l0 - m), e1 = expf(l1 - m), e2 = expf(l2 - m), e3 = expf(l3 - m);
        float inv = 1.0f / (e0 + e1 + e2 + e3);
        g_gate[t*4+0] = e0 * inv;
        g_gate[t*4+1] = e1 * inv;
        g_gate[t*4+2] = e2 * inv;
        g_gate[t*4+3] = e3 * inv;
    }
}

// ---------------------------------------------------------------------------
// Dilated 3x3 attention, channel-split 2-way, fp16 qkv reads.
// Thread pair (t, t^1) shares a position; 32 channels each; logits via shfl.
// Zero-padding softmax semantics preserved.
// ---------------------------------------------------------------------------
__global__ __launch_bounds__(256) void attn_kernel(float* __restrict__ out)
{
    const int t    = threadIdx.x;
    const int half = t & 1;
    const int n    = blockIdx.x * 128 + (t >> 1);
    const int dh = blockIdx.y;
    const int b  = blockIdx.z;
    const int i    = dh >> 1;
    const int head = dh & 1;
    const int dil  = 1 << i;
    const int h = n >> 6, w = n & 63;
    const float scale = 0.125f;

    const int ch0 = i * 128 + head * 64 + half * 32;
    const size_t base = ((size_t)b * M_ + ch0) * HW_;
    const __half* qp = g_qkv + base;
    const __half* kp = g_qkv + base + (size_t)C_ * HW_;
    const __half* vp = g_qkv + base + (size_t)2 * C_ * HW_;

    float s[9];
    int   nn[9];
    bool  ok[9];

    {
        float q[32];
        #pragma unroll
        for (int c = 0; c < 32; c++) q[c] = __half2float(qp[(size_t)c * HW_ + n]);

        #pragma unroll
        for (int j = 0; j < 9; j++) {
            const int dy = (j / 3 - 1) * dil;
            const int dx = (j % 3 - 1) * dil;
            const int hh = h + dy, ww = w + dx;
            const bool v_ok = ((unsigned)hh < 64u) && ((unsigned)ww < 64u);
            const int nnj = hh * 64 + ww;
            nn[j] = nnj; ok[j] = v_ok;
            float dot = 0.f;
            if (v_ok) {
                const __half* kk = kp + nnj;
                #pragma unroll
                for (int c = 0; c < 32; c++)
                    dot += q[c] * __half2float(kk[(size_t)c * HW_]);
            }
            dot += __shfl_xor_sync(0xFFFFFFFFu, dot, 1);
            s[j] = dot * scale;
        }
    }

    float m = s[0];
    #pragma unroll
    for (int j = 1; j < 9; j++) m = fmaxf(m, s[j]);
    float sum = 0.f;
    #pragma unroll
    for (int j = 0; j < 9; j++) { s[j] = expf(s[j] - m); sum += s[j]; }
    const float inv = 1.0f / sum;
    #pragma unroll
    for (int j = 0; j < 9; j++) s[j] *= inv;

    float acc[32];
    #pragma unroll
    for (int c = 0; c < 32; c++) acc[c] = 0.f;
    #pragma unroll
    for (int j = 0; j < 9; j++) {
        if (ok[j]) {
            const float p = s[j];
            const __half* vv = vp + nn[j];
            #pragma unroll
            for (int c = 0; c < 32; c++)
                acc[c] += p * __half2float(vv[(size_t)c * HW_]);
        }
    }

    const float g = g_gate[b * 4 + i];
    float* op = out + ((size_t)b * C_ + ch0) * HW_ + n;
    #pragma unroll
    for (int c = 0; c < 32; c++) op[(size_t)c * HW_] = g * acc[c];
}

// ---------------------------------------------------------------------------
extern "C" void kernel_launch(void* const* d_in, const int* in_sizes, int n_in,
                              void* d_out, int out_size)
{
    const float* x      = (const float*)d_in[0];
    const float* w_qkv  = (const float*)d_in[1];
    const float* w_gate = (const float*)d_in[2];
    const float* b_gate = (const float*)d_in[3];
    float* out = (float*)d_out;

    conv_w_kernel<<<(M_ * K_ / 4 + 255) / 256, 256>>>(w_qkv);
    transpose_x_kernel<<<dim3(HW_ / 32, C_ / 32, B_), dim3(32, 8)>>>(x);

    gemm_qkv_f16<<<dim3(HW_ / 128, M_ / 128, B_), 256, SM_TOT>>>();

    gate_kernel<<<1, 1024>>>(w_gate, b_gate);

    attn_kernel<<<dim3(HW_ / 128, 8, B_), 256>>>(out);
}